// round 13
// baseline (speedup 1.0000x reference)
#include <cuda_runtime.h>
#include <cuda_bf16.h>

// ---------------- scratch (device globals; no allocation allowed) ----------------
__device__ float g_A1[221184];            // layer1 eff weights, k-major: [kk(96)][ojcol(2304)]
__device__ float g_A2[688128];            // layer2 eff weights: [j][kk(384)][col(256)] (BN1-scaled in place)
__device__ unsigned short g_t1h[4718592]; // t1 bf16-hi: [b][j(9)][c(16)][n(8)]
__device__ unsigned short g_t1l[4718592]; // t1 bf16-lo
__device__ float g_t2[3670016];           // transposed: [idx(896)=c*28+j*4+l][b(4096)]
__device__ float g_t3[1310720];           // transposed: [idx(320)=o*5+j][b(4096)]
__device__ float g_red[224];              // sum1[16] ssq1[16] sum2[32] ssq2[32] sum3[64] ssq3[64]
__device__ float g_bn1[32];
__device__ float g_bn2[64];
__device__ float g_bn3[128];
__device__ float g_bias2[1792];           // [j(7)][col(256)]  BN1-shift folded through A2
__device__ float g_w3f[6144];             // [kidx(96)][o3(64)]  BN2-scale folded
__device__ float g_bias3[64];
__device__ float g_fw1f[5120];            // transposed [k(320)][o(16)], BN3-scale folded
__device__ float g_fb1f[16];

typedef unsigned long long ull;

__device__ __forceinline__ void fma2(ull& d, ull a, ull b) {
    asm("fma.rn.f32x2 %0, %1, %2, %0;" : "+l"(d) : "l"(a), "l"(b));
}
__device__ __forceinline__ ull dup2(float v) {
    ull r;
    asm("mov.b64 %0, {%1, %1};" : "=l"(r) : "f"(v));
    return r;
}
__device__ __forceinline__ float warp_sum(float v) {
    #pragma unroll
    for (int o = 16; o; o >>= 1) v += __shfl_down_sync(0xffffffffu, v, o);
    return v;
}
__device__ __forceinline__ unsigned smem_u32(const void* p) {
    unsigned a;
    asm("{ .reg .u64 t; cvta.to.shared.u64 t, %1; cvt.u32.u64 %0, t; }" : "=r"(a) : "l"(p));
    return a;
}
__device__ __forceinline__ void bfsplit(float v, unsigned short& h, unsigned short& l) {
    __nv_bfloat16 hb = __float2bfloat16(v);
    __nv_bfloat16 lb = __float2bfloat16(v - __bfloat162float(hb));
    h = *reinterpret_cast<unsigned short*>(&hb);
    l = *reinterpret_cast<unsigned short*>(&lb);
}
__device__ __forceinline__ void ldsm4(unsigned* r, unsigned addr) {
    asm volatile("ldmatrix.sync.aligned.m8n8.x4.shared.b16 {%0,%1,%2,%3}, [%4];"
        : "=r"(r[0]), "=r"(r[1]), "=r"(r[2]), "=r"(r[3]) : "r"(addr));
}
__device__ __forceinline__ void mma16816(float* d, const unsigned* a, unsigned b0, unsigned b1) {
    asm volatile("mma.sync.aligned.m16n8k16.row.col.f32.bf16.bf16.f32 "
        "{%0,%1,%2,%3}, {%4,%5,%6,%7}, {%8,%9}, {%0,%1,%2,%3};"
        : "+f"(d[0]), "+f"(d[1]), "+f"(d[2]), "+f"(d[3])
        : "r"(a[0]), "r"(a[1]), "r"(a[2]), "r"(a[3]), "r"(b0), "r"(b1));
}

__global__ void k_zero() {
    if (threadIdx.x < 224) g_red[threadIdx.x] = 0.f;
}

// Build layer1 effective weights, k-major: g_A1[kk*2304 + oj*16 + n]
__global__ void k_prep1(const float* __restrict__ w1) {
    int id = blockIdx.x * blockDim.x + threadIdx.x;
    if (id >= 221184) return;
    int n  = id & 15;
    int kk = (id >> 4) % 96;
    int oj = id / 1536;
    int o = oj / 9, j = oj % 9;
    int c = kk >> 4, p = kk & 15;
    int h = 1 << j;
    int d = p - n;
    float v = 0.f;
    if (d >= -3 * h && d <= 3 * h) {
        float t = (float)d / (float)h;
        #pragma unroll
        for (int mm = 0; mm < 7; mm++) {
            float hat = 1.f - fabsf(t - (float)(mm - 3));
            if (hat > 0.f) v += w1[(o * 6 + c) * 7 + mm] * hat;
        }
        v /= (float)h;
    }
    g_A1[kk * 2304 + oj * 16 + n] = v;
}

// Build layer2 effective weights. A2[j][kk=(c*3+r)*8+p][col=o*8+n]
__global__ void k_prep2(const float* __restrict__ w2) {
    int id = blockIdx.x * blockDim.x + threadIdx.x;
    if (id >= 688128) return;
    int col = id & 255;
    int kk  = (id >> 8) % 384;
    int j   = id / 98304;
    int o = col >> 3, n = col & 7;
    int p = kk & 7;
    int cr = kk >> 3;
    int h = 1 << j;
    int d = p - n;
    float v = 0.f;
    if (d >= -h && d <= h) {
        float t = (float)d / (float)h;
        #pragma unroll
        for (int mm = 0; mm < 3; mm++) {
            float hat = 1.f - fabsf(t - (float)(mm - 1));
            if (hat > 0.f) v += w2[(o * 48 + cr) * 3 + mm] * hat;
        }
        v /= (float)h;
    }
    g_A2[id] = v;
}

// bias2[j][col] = sum_kk sh1[c(kk)] * A2[j][kk][col]   (before scaling A2!)
__global__ void k_bias2() {
    int id = blockIdx.x * blockDim.x + threadIdx.x;
    if (id >= 1792) return;
    int j = id >> 8, col = id & 255;
    const float* base = g_A2 + j * 98304 + col;
    float s = 0.f;
    for (int c = 0; c < 16; c++) {
        float sh = g_bn1[16 + c];
        #pragma unroll 4
        for (int rem = 0; rem < 24; rem++)
            s += sh * base[(c * 24 + rem) * 256];
    }
    g_bias2[id] = s;
}

// A2 *= sc1[c(kk)]
__global__ void k_scale2() {
    int id = blockIdx.x * blockDim.x + threadIdx.x;
    if (id >= 688128) return;
    int kk = (id >> 8) % 384;
    g_A2[id] *= g_bn1[kk / 24];
}

__global__ void k_fold3(const float* __restrict__ w3) {
    int id = blockIdx.x * blockDim.x + threadIdx.x;
    if (id < 6144) {
        int kidx = id >> 6, o = id & 63;
        int c = kidx / 3, rr = kidx - c * 3;
        g_w3f[id] = w3[(o * 32 + c) * 3 + rr] * g_bn2[c];
    }
    if (id < 64) {
        float s = 0.f;
        for (int c = 0; c < 32; c++) {
            float sh = g_bn2[32 + c];
            s += (w3[(id * 32 + c) * 3] + w3[(id * 32 + c) * 3 + 1] + w3[(id * 32 + c) * 3 + 2]) * sh;
        }
        g_bias3[id] = s;
    }
}

__global__ void k_foldfc(const float* __restrict__ fw1, const float* __restrict__ fb1) {
    int id = blockIdx.x * blockDim.x + threadIdx.x;
    if (id < 5120) {
        int o = id / 320, k = id - o * 320;
        g_fw1f[k * 16 + o] = fw1[id] * g_bn3[k / 5];
    }
    if (id < 16) {
        float s = fb1[id];
        for (int k = 0; k < 320; k++)
            s += fw1[id * 320 + k] * g_bn3[64 + k / 5];
        g_fb1f[id] = s;
    }
}

// ---------------------------------------------------------------------------
// Layer1 (HMMA): block 128 rows x 128 cols (8 oj), K=96, split-bf16 3 passes.
// smem: Ah|Al|Bh|Bl each [128][104 bf16] (208 B rows) = 4*26624 = 106496 B.
// 8 warps: warp = 32 rows x 64 cols (2 m-tiles x 8 n-tiles of m16n8k16).
// Epilogue: pre[128][132] (reuse), pool(4,s2,p1)+relu+stats, t1 -> bf16 hi/lo.
// ---------------------------------------------------------------------------
__global__ void __launch_bounds__(256, 2) k_layer1(const float* __restrict__ x) {
    extern __shared__ __align__(16) char dsm[];
    char* Ah = dsm;
    char* Al = dsm + 26624;
    char* Bh = dsm + 53248;
    char* Bl = dsm + 79872;
    const int t = threadIdx.x, lane = t & 31, w = t >> 5;
    const int b0 = blockIdx.x * 128;
    const int oj0 = blockIdx.y * 8;

    // stage A = x[128][96] as hi/lo bf16, [row][k] rows of 208 B
    for (int i = t; i < 3072; i += 256) {
        int r = i & 127, q = (i >> 7) * 4;
        float4 v = *reinterpret_cast<const float4*>(x + (long)(b0 + r) * 96 + q);
        unsigned short h0, l0, h1, l1, h2, l2, h3, l3;
        bfsplit(v.x, h0, l0); bfsplit(v.y, h1, l1);
        bfsplit(v.z, h2, l2); bfsplit(v.w, h3, l3);
        *reinterpret_cast<uint2*>(Ah + r * 208 + q * 2) =
            make_uint2((unsigned)h0 | ((unsigned)h1 << 16), (unsigned)h2 | ((unsigned)h3 << 16));
        *reinterpret_cast<uint2*>(Al + r * 208 + q * 2) =
            make_uint2((unsigned)l0 | ((unsigned)l1 << 16), (unsigned)l2 | ((unsigned)l3 << 16));
    }
    // stage B: [col][k] from g_A1[kk][2304]
    for (int i = t; i < 12288; i += 256) {
        int col = i & 127, kk = i >> 7;
        float v = g_A1[(long)kk * 2304 + oj0 * 16 + col];
        unsigned short h, l; bfsplit(v, h, l);
        *reinterpret_cast<unsigned short*>(Bh + col * 208 + kk * 2) = h;
        *reinterpret_cast<unsigned short*>(Bl + col * 208 + kk * 2) = l;
    }
    __syncthreads();

    float d[2][8][4];
    #pragma unroll
    for (int mt = 0; mt < 2; mt++)
        #pragma unroll
        for (int nt = 0; nt < 8; nt++)
            #pragma unroll
            for (int e = 0; e < 4; e++) d[mt][nt][e] = 0.f;

    const int R0 = (w & 3) * 32, C0 = (w >> 2) * 64;
    const unsigned offA = (unsigned)((R0 + (lane & 7) + ((lane >> 3) & 1) * 8) * 208 + ((lane >> 4) & 1) * 16);
    const unsigned offB = (unsigned)((C0 + (lane & 7) + ((lane >> 4) & 1) * 8) * 208 + ((lane >> 3) & 1) * 16);
    const unsigned bAh = smem_u32(Ah), bAl = smem_u32(Al);
    const unsigned bBh = smem_u32(Bh), bBl = smem_u32(Bl);

    for (int pass = 0; pass < 3; pass++) {
        unsigned aB = (pass == 1 ? bAl : bAh) + offA;
        unsigned bB = (pass == 2 ? bBl : bBh) + offB;
        #pragma unroll
        for (int ks = 0; ks < 6; ks++) {
            unsigned A0[4], A1[4];
            ldsm4(A0, aB + ks * 32);
            ldsm4(A1, aB + 16 * 208 + ks * 32);
            #pragma unroll
            for (int ntp = 0; ntp < 4; ntp++) {
                unsigned Bf[4];
                ldsm4(Bf, bB + ntp * (16 * 208) + ks * 32);
                mma16816(d[0][2 * ntp],     A0, Bf[0], Bf[1]);
                mma16816(d[1][2 * ntp],     A1, Bf[0], Bf[1]);
                mma16816(d[0][2 * ntp + 1], A0, Bf[2], Bf[3]);
                mma16816(d[1][2 * ntp + 1], A1, Bf[2], Bf[3]);
            }
        }
    }
    __syncthreads();

    // spill to pre[128][132]
    float* pre = reinterpret_cast<float*>(dsm);
    const int lr = lane >> 2, lc2 = (lane & 3) * 2;
    #pragma unroll
    for (int mt = 0; mt < 2; mt++)
        #pragma unroll
        for (int nt = 0; nt < 8; nt++) {
            int row = R0 + 16 * mt + lr, col = C0 + 8 * nt + lc2;
            *reinterpret_cast<float2*>(pre + row * 132 + col)       = make_float2(d[mt][nt][0], d[mt][nt][1]);
            *reinterpret_cast<float2*>(pre + (row + 8) * 132 + col) = make_float2(d[mt][nt][2], d[mt][nt][3]);
        }
    __syncthreads();

    // Pool(4,s2,p1)+relu+stats; store t1 as bf16 hi/lo [b][j][c][n]
    const int row = t & 127, half = t >> 7;
    const float* pr = pre + row * 132;
    #pragma unroll
    for (int gg = 0; gg < 4; gg++) {
        int g = half * 4 + gg;
        int oj = oj0 + g;
        int o = oj / 9, jj = oj - o * 9;
        __align__(16) unsigned short hs[8], ls[8];
        float s = 0.f, ss = 0.f;
        #pragma unroll
        for (int k = 0; k < 8; k++) {
            int lo = (2 * k - 1 < 0) ? 0 : 2 * k - 1;
            int hi = (2 * k + 2 > 15) ? 15 : 2 * k + 2;
            float m = pr[g * 16 + lo];
            for (int nn = lo + 1; nn <= hi; nn++) m = fmaxf(m, pr[g * 16 + nn]);
            m = fmaxf(m, 0.f);
            bfsplit(m, hs[k], ls[k]);
            s += m; ss += m * m;
        }
        long dst = (long)(b0 + row) * 1152 + jj * 128 + o * 8;
        *reinterpret_cast<uint4*>(g_t1h + dst) = *reinterpret_cast<uint4*>(hs);
        *reinterpret_cast<uint4*>(g_t1l + dst) = *reinterpret_cast<uint4*>(ls);
        float sA = warp_sum(s), ssA = warp_sum(ss);
        if ((t & 31) == 0) { atomicAdd(&g_red[o], sA); atomicAdd(&g_red[16 + o], ssA); }
    }
}

__global__ void k_bnparam(const float* __restrict__ g, const float* __restrict__ b, int layer) {
    int c = threadIdx.x;
    int nch, off; float count; float* bn;
    if (layer == 1)      { nch = 16; off = 0;  count = 294912.f; bn = g_bn1; }
    else if (layer == 2) { nch = 32; off = 32; count = 114688.f; bn = g_bn2; }
    else                 { nch = 64; off = 96; count = 20480.f;  bn = g_bn3; }
    if (c >= nch) return;
    float sum = g_red[off + c], ssq = g_red[off + nch + c];
    float mean = sum / count;
    float var = ssq / count - mean * mean;
    float sc = g[c] * rsqrtf(var + 2e-5f);
    bn[c] = sc;
    bn[nch + c] = b[c] - mean * sc;
}

// ---------------------------------------------------------------------------
// Layer2 (HMMA): per (b-tile, cb, j): 128 rows x 128 cols (16 o2), K=384 in
// 4 chunks of 96, split-bf16 3 passes per chunk (stage once, 3 passes).
// A from prestored bf16 hi/lo t1 (pure 16B copies). bias2 added at spill.
// ---------------------------------------------------------------------------
__global__ void __launch_bounds__(256, 2) k_layer2() {
    extern __shared__ __align__(16) char dsm[];
    char* Ah = dsm;
    char* Al = dsm + 26624;
    char* Bh = dsm + 53248;
    char* Bl = dsm + 79872;
    const int t = threadIdx.x, lane = t & 31, w = t >> 5;
    const int b0 = blockIdx.x * 128;
    const int cb = blockIdx.y;
    const int j  = blockIdx.z;

    float d[2][8][4];
    #pragma unroll
    for (int mt = 0; mt < 2; mt++)
        #pragma unroll
        for (int nt = 0; nt < 8; nt++)
            #pragma unroll
            for (int e = 0; e < 4; e++) d[mt][nt][e] = 0.f;

    const int R0 = (w & 3) * 32, C0 = (w >> 2) * 64;
    const unsigned offA = (unsigned)((R0 + (lane & 7) + ((lane >> 3) & 1) * 8) * 208 + ((lane >> 4) & 1) * 16);
    const unsigned offB = (unsigned)((C0 + (lane & 7) + ((lane >> 4) & 1) * 8) * 208 + ((lane >> 3) & 1) * 16);
    const unsigned bAh = smem_u32(Ah), bAl = smem_u32(Al);
    const unsigned bBh = smem_u32(Bh), bBl = smem_u32(Bl);

    for (int kt = 0; kt < 4; kt++) {
        __syncthreads();
        // stage A chunk: [row][k 96] from g_t1h/g_t1l (16B copies)
        for (int i = t; i < 1536; i += 256) {
            int r = i & 127, m = i >> 7;        // m 0..11
            int cc = m / 3, rr = m - cc * 3;
            long src = (long)(b0 + r) * 1152 + (j + rr) * 128 + (kt * 4 + cc) * 8;
            int doff = r * 208 + (cc * 24 + rr * 8) * 2;
            *reinterpret_cast<uint4*>(Ah + doff) = *reinterpret_cast<const uint4*>(g_t1h + src);
            *reinterpret_cast<uint4*>(Al + doff) = *reinterpret_cast<const uint4*>(g_t1l + src);
        }
        // stage B chunk: [col][k 96] from g_A2 (scaled)
        for (int i = t; i < 12288; i += 256) {
            int col = i & 127, kk = i >> 7;
            float v = g_A2[(long)j * 98304 + (long)(kt * 96 + kk) * 256 + cb * 128 + col];
            unsigned short h, l; bfsplit(v, h, l);
            *reinterpret_cast<unsigned short*>(Bh + col * 208 + kk * 2) = h;
            *reinterpret_cast<unsigned short*>(Bl + col * 208 + kk * 2) = l;
        }
        __syncthreads();

        for (int pass = 0; pass < 3; pass++) {
            unsigned aB = (pass == 1 ? bAl : bAh) + offA;
            unsigned bB = (pass == 2 ? bBl : bBh) + offB;
            #pragma unroll
            for (int ks = 0; ks < 6; ks++) {
                unsigned A0[4], A1[4];
                ldsm4(A0, aB + ks * 32);
                ldsm4(A1, aB + 16 * 208 + ks * 32);
                #pragma unroll
                for (int ntp = 0; ntp < 4; ntp++) {
                    unsigned Bf[4];
                    ldsm4(Bf, bB + ntp * (16 * 208) + ks * 32);
                    mma16816(d[0][2 * ntp],     A0, Bf[0], Bf[1]);
                    mma16816(d[1][2 * ntp],     A1, Bf[0], Bf[1]);
                    mma16816(d[0][2 * ntp + 1], A0, Bf[2], Bf[3]);
                    mma16816(d[1][2 * ntp + 1], A1, Bf[2], Bf[3]);
                }
            }
        }
    }
    __syncthreads();

    // spill to pre[128][132] with bias2 added
    float* pre = reinterpret_cast<float*>(dsm);
    const int lr = lane >> 2, lc2 = (lane & 3) * 2;
    #pragma unroll
    for (int mt = 0; mt < 2; mt++)
        #pragma unroll
        for (int nt = 0; nt < 8; nt++) {
            int col = C0 + 8 * nt + lc2;
            float2 bv = *reinterpret_cast<const float2*>(g_bias2 + j * 256 + cb * 128 + col);
            int row = R0 + 16 * mt + lr;
            *reinterpret_cast<float2*>(pre + row * 132 + col) =
                make_float2(d[mt][nt][0] + bv.x, d[mt][nt][1] + bv.y);
            *reinterpret_cast<float2*>(pre + (row + 8) * 132 + col) =
                make_float2(d[mt][nt][2] + bv.x, d[mt][nt][3] + bv.y);
        }
    __syncthreads();

    // Pool(4,s2,p1)+relu+stats -> transposed g_t2[idx][b]
    const int row = t & 127, half = t >> 7;
    const float* pr = pre + row * 132;
    #pragma unroll
    for (int ol = 0; ol < 8; ol++) {
        int lc = half * 8 + ol;
        int o2g = cb * 16 + lc;
        float s = 0.f, ss = 0.f;
        #pragma unroll
        for (int k = 0; k < 4; k++) {
            int lo = (2 * k - 1 < 0) ? 0 : 2 * k - 1;
            int hi = (2 * k + 2 > 7) ? 7 : 2 * k + 2;
            float m = pr[lc * 8 + lo];
            for (int nn = lo + 1; nn <= hi; nn++) m = fmaxf(m, pr[lc * 8 + nn]);
            m = fmaxf(m, 0.f);
            g_t2[(long)(o2g * 28 + j * 4 + k) * 4096 + b0 + row] = m;
            s += m; ss += m * m;
        }
        float sA = warp_sum(s), ssA = warp_sum(ss);
        if ((t & 31) == 0) { atomicAdd(&g_red[32 + o2g], sA); atomicAdd(&g_red[64 + o2g], ssA); }
    }
}

// ---------------------------------------------------------------------------
// Layer3: unchanged from R10 (f32x2 row-pair). smem 96256 B, 2 blocks/SM.
// ---------------------------------------------------------------------------
__global__ void __launch_bounds__(256, 2) k_layer3() {
    extern __shared__ float sm[];
    float* actsT = sm;             // [896][20]
    float* ws    = sm + 17920;     // [96][64]
    __shared__ float st[128];
    const int t = threadIdx.x;
    const int b0 = blockIdx.x * 16;

    for (int i = t; i < 3584; i += 256) {
        int idx = i >> 2, r4 = (i & 3) * 4;
        float4 v = *reinterpret_cast<const float4*>(g_t2 + (long)idx * 4096 + b0 + r4);
        *reinterpret_cast<float4*>(actsT + idx * 20 + r4) = v;
    }
    for (int i = t; i < 6144; i += 256) ws[i] = g_w3f[i];
    if (t < 128) st[t] = 0.f;
    __syncthreads();

    const int o3 = t & 63, rpg = t >> 6;
    const ull* a64 = reinterpret_cast<const ull*>(actsT);
    const float invj[5] = {1.f, 0.5f, 0.25f, 0.125f, 0.0625f};
    const float bias = g_bias3[o3];
    float s = 0.f, ssq = 0.f;

    #pragma unroll
    for (int hf = 0; hf < 2; hf++) {
        const int rp = rpg + 4 * hf;
        ull accp[15];
        #pragma unroll
        for (int i = 0; i < 15; i++) accp[i] = 0ull;

        for (int c = 0; c < 32; c++) {
            ull av[21];
            #pragma unroll
            for (int m = 0; m < 7; m++)
                #pragma unroll
                for (int l = 0; l < 3; l++)
                    av[m * 3 + l] = a64[(c * 28 + m * 4 + l) * 10 + rp];
            ull w0 = dup2(ws[(c * 3 + 0) * 64 + o3]);
            ull w1 = dup2(ws[(c * 3 + 1) * 64 + o3]);
            ull w2 = dup2(ws[(c * 3 + 2) * 64 + o3]);
            #pragma unroll
            for (int jj = 0; jj < 5; jj++)
                #pragma unroll
                for (int l = 0; l < 3; l++) {
                    fma2(accp[jj * 3 + l], w0, av[(jj + 0) * 3 + l]);
                    fma2(accp[jj * 3 + l], w1, av[(jj + 1) * 3 + l]);
                    fma2(accp[jj * 3 + l], w2, av[(jj + 2) * 3 + l]);
                }
        }
        #pragma unroll
        for (int jj = 0; jj < 5; jj++) {
            float2 v0 = *reinterpret_cast<float2*>(&accp[jj * 3 + 0]);
            float2 v1 = *reinterpret_cast<float2*>(&accp[jj * 3 + 1]);
            float2 v2 = *reinterpret_cast<float2*>(&accp[jj * 3 + 2]);
            float mx = (fmaxf(fmaxf(v0.x, v1.x), v2.x) + bias) * invj[jj];
            float my = (fmaxf(fmaxf(v0.y, v1.y), v2.y) + bias) * invj[jj];
            mx = fmaxf(mx, 0.f); my = fmaxf(my, 0.f);
            *reinterpret_cast<float2*>(g_t3 + (long)(o3 * 5 + jj) * 4096 + b0 + 2 * rp) =
                make_float2(mx, my);
            s += mx + my; ssq += mx * mx + my * my;
        }
    }
    atomicAdd(&st[o3], s);
    atomicAdd(&st[64 + o3], ssq);
    __syncthreads();
    if (t < 64) { atomicAdd(&g_red[96 + t], st[t]); atomicAdd(&g_red[160 + t], st[64 + t]); }
}

// 3-layer MLP; BN3 prefolded. Unchanged from R10.
__global__ void __launch_bounds__(128) k_fc(const float* __restrict__ fw2, const float* __restrict__ fb2,
                                            const float* __restrict__ fw3, const float* __restrict__ fb3,
                                            float* __restrict__ out) {
    __shared__ float w1s[5120];
    __shared__ float vtT[32 * 132];
    __shared__ float w2s[256];
    __shared__ float w3s[272];
    __shared__ float b1s[16], b2s[16], b3s[17];
    int t = threadIdx.x;
    int bbase = blockIdx.x * 128;
    for (int i = t; i < 5120; i += 128) w1s[i] = g_fw1f[i];
    for (int i = t; i < 256; i += 128) w2s[i] = fw2[i];
    for (int i = t; i < 272; i += 128) w3s[i] = fw3[i];
    if (t < 16) { b1s[t] = g_fb1f[t]; b2s[t] = fb2[t]; }
    if (t < 17) b3s[t] = fb3[t];
    __syncthreads();

    float h1[16];
    #pragma unroll
    for (int o = 0; o < 16; o++) h1[o] = b1s[o];

    for (int i0 = 0; i0 < 320; i0 += 32) {
        __syncthreads();
        for (int i = t; i < 1024; i += 128) {
            int c2 = i >> 5, r4 = (i & 31) * 4;
            float4 v = *reinterpret_cast<const float4*>(g_t3 + (long)(i0 + c2) * 4096 + bbase + r4);
            *reinterpret_cast<float4*>(vtT + c2 * 132 + r4) = v;
        }
        __syncthreads();
        #pragma unroll 4
        for (int c2 = 0; c2 < 32; c2++) {
            float v = vtT[c2 * 132 + t];
            const float* wr = &w1s[(i0 + c2) * 16];
            #pragma unroll
            for (int o = 0; o < 16; o++) h1[o] += v * wr[o];
        }
    }
    float h2[16];
    #pragma unroll
    for (int o = 0; o < 16; o++) {
        float a = b2s[o];
        #pragma unroll
        for (int k = 0; k < 16; k++) a += h1[k] * w2s[o * 16 + k];
        h2[o] = a;
    }
    int b = bbase + t;
    #pragma unroll
    for (int o = 0; o < 17; o++) {
        float a = b3s[o];
        #pragma unroll
        for (int k = 0; k < 16; k++) a += h2[k] * w3s[o * 16 + k];
        out[b * 17 + o] = a;
    }
}

extern "C" void kernel_launch(void* const* d_in, const int* in_sizes, int n_in,
                              void* d_out, int out_size) {
    const float* x   = (const float*)d_in[0];
    const float* w1  = (const float*)d_in[1];
    const float* w2  = (const float*)d_in[2];
    const float* w3  = (const float*)d_in[3];
    const float* g1  = (const float*)d_in[4];
    const float* b1  = (const float*)d_in[5];
    const float* g2  = (const float*)d_in[6];
    const float* b2  = (const float*)d_in[7];
    const float* g3  = (const float*)d_in[8];
    const float* b3  = (const float*)d_in[9];
    const float* fw1 = (const float*)d_in[10];
    const float* fb1 = (const float*)d_in[11];
    const float* fw2 = (const float*)d_in[12];
    const float* fb2 = (const float*)d_in[13];
    const float* fw3 = (const float*)d_in[14];
    const float* fb3 = (const float*)d_in[15];
    float* out = (float*)d_out;

    cudaFuncSetAttribute(k_layer1, cudaFuncAttributeMaxDynamicSharedMemorySize, 106496);
    cudaFuncSetAttribute(k_layer2, cudaFuncAttributeMaxDynamicSharedMemorySize, 106496);
    cudaFuncSetAttribute(k_layer3, cudaFuncAttributeMaxDynamicSharedMemorySize, 96256);

    k_zero<<<1, 256>>>();
    k_prep1<<<(221184 + 255) / 256, 256>>>(w1);
    k_prep2<<<(688128 + 255) / 256, 256>>>(w2);
    k_layer1<<<dim3(32, 18), 256, 106496>>>(x);
    k_bnparam<<<1, 64>>>(g1, b1, 1);
    k_bias2<<<7, 256>>>();
    k_scale2<<<2688, 256>>>();
    k_layer2<<<dim3(32, 2, 7), 256, 106496>>>();
    k_bnparam<<<1, 64>>>(g2, b2, 2);
    k_fold3<<<24, 256>>>(w3);
    k_layer3<<<256, 256, 96256>>>();
    k_bnparam<<<1, 64>>>(g3, b3, 3);
    k_foldfc<<<21, 256>>>(fw1, fb1);
    k_fc<<<32, 128>>>(fw2, fb2, fw3, fb3, out);
}

// round 14
// speedup vs baseline: 1.4781x; 1.4781x over previous
#include <cuda_runtime.h>
#include <cuda_bf16.h>

// ---------------- scratch (device globals; no allocation allowed) ----------------
__device__ float g_A2[688128];            // layer2 eff weights fp32: [j][kk(384)][col(256)]
__device__ unsigned short g_A1h[221184];  // layer1 weights bf16-hi: [col(2304)][k(96)]
__device__ unsigned short g_A1l[221184];  // layer1 weights bf16-lo
__device__ unsigned short g_A2h[688128];  // layer2 weights bf16-hi: [j][col(256)][k(384)] (BN1-scaled)
__device__ unsigned short g_A2l[688128];  // layer2 weights bf16-lo
__device__ unsigned short g_t1h[4718592]; // t1 bf16-hi: [b][j(9)][c(16)][n(8)]
__device__ unsigned short g_t1l[4718592]; // t1 bf16-lo
__device__ float g_t2[3670016];           // transposed: [idx(896)=c*28+j*4+l][b(4096)]
__device__ float g_t3[1310720];           // transposed: [idx(320)=o*5+j][b(4096)]
__device__ float g_red[224];              // sum1[16] ssq1[16] sum2[32] ssq2[32] sum3[64] ssq3[64]
__device__ float g_bn1[32];
__device__ float g_bn2[64];
__device__ float g_bn3[128];
__device__ float g_bias2[1792];           // [j(7)][col(256)]
__device__ float g_w3f[6144];             // [kidx(96)][o3(64)]  BN2-scale folded
__device__ float g_bias3[64];
__device__ float g_fw1f[5120];            // transposed [k(320)][o(16)], BN3-scale folded
__device__ float g_fb1f[16];

typedef unsigned long long ull;

__device__ __forceinline__ void fma2(ull& d, ull a, ull b) {
    asm("fma.rn.f32x2 %0, %1, %2, %0;" : "+l"(d) : "l"(a), "l"(b));
}
__device__ __forceinline__ ull dup2(float v) {
    ull r;
    asm("mov.b64 %0, {%1, %1};" : "=l"(r) : "f"(v));
    return r;
}
__device__ __forceinline__ float warp_sum(float v) {
    #pragma unroll
    for (int o = 16; o; o >>= 1) v += __shfl_down_sync(0xffffffffu, v, o);
    return v;
}
__device__ __forceinline__ unsigned smem_u32(const void* p) {
    unsigned a;
    asm("{ .reg .u64 t; cvta.to.shared.u64 t, %1; cvt.u32.u64 %0, t; }" : "=r"(a) : "l"(p));
    return a;
}
__device__ __forceinline__ void bfsplit(float v, unsigned short& h, unsigned short& l) {
    __nv_bfloat16 hb = __float2bfloat16(v);
    __nv_bfloat16 lb = __float2bfloat16(v - __bfloat162float(hb));
    h = *reinterpret_cast<unsigned short*>(&hb);
    l = *reinterpret_cast<unsigned short*>(&lb);
}
__device__ __forceinline__ void ldsm4(unsigned* r, unsigned addr) {
    asm volatile("ldmatrix.sync.aligned.m8n8.x4.shared.b16 {%0,%1,%2,%3}, [%4];"
        : "=r"(r[0]), "=r"(r[1]), "=r"(r[2]), "=r"(r[3]) : "r"(addr));
}
__device__ __forceinline__ void mma16816(float* d, const unsigned* a, unsigned b0, unsigned b1) {
    asm volatile("mma.sync.aligned.m16n8k16.row.col.f32.bf16.bf16.f32 "
        "{%0,%1,%2,%3}, {%4,%5,%6,%7}, {%8,%9}, {%0,%1,%2,%3};"
        : "+f"(d[0]), "+f"(d[1]), "+f"(d[2]), "+f"(d[3])
        : "r"(a[0]), "r"(a[1]), "r"(a[2]), "r"(a[3]), "r"(b0), "r"(b1));
}

__global__ void k_zero() {
    if (threadIdx.x < 224) g_red[threadIdx.x] = 0.f;
}

// Build layer1 effective weights -> bf16 hi/lo in [col][k] layout.
__global__ void k_prep1(const float* __restrict__ w1) {
    int id = blockIdx.x * blockDim.x + threadIdx.x;
    if (id >= 221184) return;
    int n  = id & 15;
    int kk = (id >> 4) % 96;
    int oj = id / 1536;
    int o = oj / 9, j = oj % 9;
    int c = kk >> 4, p = kk & 15;
    int h = 1 << j;
    int d = p - n;
    float v = 0.f;
    if (d >= -3 * h && d <= 3 * h) {
        float t = (float)d / (float)h;
        #pragma unroll
        for (int mm = 0; mm < 7; mm++) {
            float hat = 1.f - fabsf(t - (float)(mm - 3));
            if (hat > 0.f) v += w1[(o * 6 + c) * 7 + mm] * hat;
        }
        v /= (float)h;
    }
    unsigned short hi, lo;
    bfsplit(v, hi, lo);
    long dst = (long)(oj * 16 + n) * 96 + kk;
    g_A1h[dst] = hi;
    g_A1l[dst] = lo;
}

// Build layer2 effective weights (fp32). A2[j][kk=(c*3+r)*8+p][col=o*8+n]
__global__ void k_prep2(const float* __restrict__ w2) {
    int id = blockIdx.x * blockDim.x + threadIdx.x;
    if (id >= 688128) return;
    int col = id & 255;
    int kk  = (id >> 8) % 384;
    int j   = id / 98304;
    int o = col >> 3, n = col & 7;
    int p = kk & 7;
    int cr = kk >> 3;
    int h = 1 << j;
    int d = p - n;
    float v = 0.f;
    if (d >= -h && d <= h) {
        float t = (float)d / (float)h;
        #pragma unroll
        for (int mm = 0; mm < 3; mm++) {
            float hat = 1.f - fabsf(t - (float)(mm - 1));
            if (hat > 0.f) v += w2[(o * 48 + cr) * 3 + mm] * hat;
        }
        v /= (float)h;
    }
    g_A2[id] = v;
}

// bias2[j][col] = sum_kk sh1[c(kk)] * A2[j][kk][col]   (unscaled A2)
__global__ void k_bias2() {
    int id = blockIdx.x * blockDim.x + threadIdx.x;
    if (id >= 1792) return;
    int j = id >> 8, col = id & 255;
    const float* base = g_A2 + j * 98304 + col;
    float s = 0.f;
    for (int c = 0; c < 16; c++) {
        float sh = g_bn1[16 + c];
        #pragma unroll 4
        for (int rem = 0; rem < 24; rem++)
            s += sh * base[(c * 24 + rem) * 256];
    }
    g_bias2[id] = s;
}

// Scale A2 by BN1 and convert to bf16 hi/lo in [j][col][k] layout.
__global__ void k_conv2() {
    int id = blockIdx.x * blockDim.x + threadIdx.x;
    if (id >= 688128) return;
    int col = id & 255;
    int kk  = (id >> 8) % 384;
    int j   = id / 98304;
    float v = g_A2[id] * g_bn1[kk / 24];
    unsigned short h, l;
    bfsplit(v, h, l);
    long dst = (long)(j * 256 + col) * 384 + kk;
    g_A2h[dst] = h;
    g_A2l[dst] = l;
}

__global__ void k_fold3(const float* __restrict__ w3) {
    int id = blockIdx.x * blockDim.x + threadIdx.x;
    if (id < 6144) {
        int kidx = id >> 6, o = id & 63;
        int c = kidx / 3, rr = kidx - c * 3;
        g_w3f[id] = w3[(o * 32 + c) * 3 + rr] * g_bn2[c];
    }
    if (id < 64) {
        float s = 0.f;
        for (int c = 0; c < 32; c++) {
            float sh = g_bn2[32 + c];
            s += (w3[(id * 32 + c) * 3] + w3[(id * 32 + c) * 3 + 1] + w3[(id * 32 + c) * 3 + 2]) * sh;
        }
        g_bias3[id] = s;
    }
}

__global__ void k_foldfc(const float* __restrict__ fw1, const float* __restrict__ fb1) {
    int id = blockIdx.x * blockDim.x + threadIdx.x;
    if (id < 5120) {
        int o = id / 320, k = id - o * 320;
        g_fw1f[k * 16 + o] = fw1[id] * g_bn3[k / 5];
    }
    if (id < 16) {
        float s = fb1[id];
        for (int k = 0; k < 320; k++)
            s += fw1[id * 320 + k] * g_bn3[64 + k / 5];
        g_fb1f[id] = s;
    }
}

// ---------------------------------------------------------------------------
// Layer1 (HMMA): block 128 rows x 128 cols, K=96, split-bf16 3 passes.
// B staging = pure uint4 copies from prebuilt g_A1h/g_A1l.
// ---------------------------------------------------------------------------
__global__ void __launch_bounds__(256, 2) k_layer1(const float* __restrict__ x) {
    extern __shared__ __align__(16) char dsm[];
    char* Ah = dsm;
    char* Al = dsm + 26624;
    char* Bh = dsm + 53248;
    char* Bl = dsm + 79872;
    const int t = threadIdx.x, lane = t & 31, w = t >> 5;
    const int b0 = blockIdx.x * 128;
    const int oj0 = blockIdx.y * 8;

    // stage A = x[128][96] as hi/lo bf16
    for (int i = t; i < 3072; i += 256) {
        int r = i & 127, q = (i >> 7) * 4;
        float4 v = *reinterpret_cast<const float4*>(x + (long)(b0 + r) * 96 + q);
        unsigned short h0, l0, h1, l1, h2, l2, h3, l3;
        bfsplit(v.x, h0, l0); bfsplit(v.y, h1, l1);
        bfsplit(v.z, h2, l2); bfsplit(v.w, h3, l3);
        *reinterpret_cast<uint2*>(Ah + r * 208 + q * 2) =
            make_uint2((unsigned)h0 | ((unsigned)h1 << 16), (unsigned)h2 | ((unsigned)h3 << 16));
        *reinterpret_cast<uint2*>(Al + r * 208 + q * 2) =
            make_uint2((unsigned)l0 | ((unsigned)l1 << 16), (unsigned)l2 | ((unsigned)l3 << 16));
    }
    // stage B: uint4 copies (col rows of 192 B = 12 uint4)
    for (int i = t; i < 1536; i += 256) {
        int col = i / 12, q = i - col * 12;
        long src = (long)(oj0 * 16 + col) * 96 + q * 8;
        int doff = col * 208 + q * 16;
        *reinterpret_cast<uint4*>(Bh + doff) = *reinterpret_cast<const uint4*>(g_A1h + src);
        *reinterpret_cast<uint4*>(Bl + doff) = *reinterpret_cast<const uint4*>(g_A1l + src);
    }
    __syncthreads();

    float d[2][8][4];
    #pragma unroll
    for (int mt = 0; mt < 2; mt++)
        #pragma unroll
        for (int nt = 0; nt < 8; nt++)
            #pragma unroll
            for (int e = 0; e < 4; e++) d[mt][nt][e] = 0.f;

    const int R0 = (w & 3) * 32, C0 = (w >> 2) * 64;
    const unsigned offA = (unsigned)((R0 + (lane & 7) + ((lane >> 3) & 1) * 8) * 208 + ((lane >> 4) & 1) * 16);
    const unsigned offB = (unsigned)((C0 + (lane & 7) + ((lane >> 4) & 1) * 8) * 208 + ((lane >> 3) & 1) * 16);
    const unsigned bAh = smem_u32(Ah), bAl = smem_u32(Al);
    const unsigned bBh = smem_u32(Bh), bBl = smem_u32(Bl);

    for (int pass = 0; pass < 3; pass++) {
        unsigned aB = (pass == 1 ? bAl : bAh) + offA;
        unsigned bB = (pass == 2 ? bBl : bBh) + offB;
        #pragma unroll
        for (int ks = 0; ks < 6; ks++) {
            unsigned A0[4], A1[4];
            ldsm4(A0, aB + ks * 32);
            ldsm4(A1, aB + 16 * 208 + ks * 32);
            #pragma unroll
            for (int ntp = 0; ntp < 4; ntp++) {
                unsigned Bf[4];
                ldsm4(Bf, bB + ntp * (16 * 208) + ks * 32);
                mma16816(d[0][2 * ntp],     A0, Bf[0], Bf[1]);
                mma16816(d[1][2 * ntp],     A1, Bf[0], Bf[1]);
                mma16816(d[0][2 * ntp + 1], A0, Bf[2], Bf[3]);
                mma16816(d[1][2 * ntp + 1], A1, Bf[2], Bf[3]);
            }
        }
    }
    __syncthreads();

    float* pre = reinterpret_cast<float*>(dsm);
    const int lr = lane >> 2, lc2 = (lane & 3) * 2;
    #pragma unroll
    for (int mt = 0; mt < 2; mt++)
        #pragma unroll
        for (int nt = 0; nt < 8; nt++) {
            int row = R0 + 16 * mt + lr, col = C0 + 8 * nt + lc2;
            *reinterpret_cast<float2*>(pre + row * 132 + col)       = make_float2(d[mt][nt][0], d[mt][nt][1]);
            *reinterpret_cast<float2*>(pre + (row + 8) * 132 + col) = make_float2(d[mt][nt][2], d[mt][nt][3]);
        }
    __syncthreads();

    // Pool(4,s2,p1)+relu+stats; store t1 as bf16 hi/lo [b][j][c][n]
    const int row = t & 127, half = t >> 7;
    const float* pr = pre + row * 132;
    #pragma unroll
    for (int gg = 0; gg < 4; gg++) {
        int g = half * 4 + gg;
        int oj = oj0 + g;
        int o = oj / 9, jj = oj - o * 9;
        __align__(16) unsigned short hs[8], ls[8];
        float s = 0.f, ss = 0.f;
        #pragma unroll
        for (int k = 0; k < 8; k++) {
            int lo = (2 * k - 1 < 0) ? 0 : 2 * k - 1;
            int hi = (2 * k + 2 > 15) ? 15 : 2 * k + 2;
            float m = pr[g * 16 + lo];
            for (int nn = lo + 1; nn <= hi; nn++) m = fmaxf(m, pr[g * 16 + nn]);
            m = fmaxf(m, 0.f);
            bfsplit(m, hs[k], ls[k]);
            s += m; ss += m * m;
        }
        long dst = (long)(b0 + row) * 1152 + jj * 128 + o * 8;
        *reinterpret_cast<uint4*>(g_t1h + dst) = *reinterpret_cast<uint4*>(hs);
        *reinterpret_cast<uint4*>(g_t1l + dst) = *reinterpret_cast<uint4*>(ls);
        float sA = warp_sum(s), ssA = warp_sum(ss);
        if ((t & 31) == 0) { atomicAdd(&g_red[o], sA); atomicAdd(&g_red[16 + o], ssA); }
    }
}

__global__ void k_bnparam(const float* __restrict__ g, const float* __restrict__ b, int layer) {
    int c = threadIdx.x;
    int nch, off; float count; float* bn;
    if (layer == 1)      { nch = 16; off = 0;  count = 294912.f; bn = g_bn1; }
    else if (layer == 2) { nch = 32; off = 32; count = 114688.f; bn = g_bn2; }
    else                 { nch = 64; off = 96; count = 20480.f;  bn = g_bn3; }
    if (c >= nch) return;
    float sum = g_red[off + c], ssq = g_red[off + nch + c];
    float mean = sum / count;
    float var = ssq / count - mean * mean;
    float sc = g[c] * rsqrtf(var + 2e-5f);
    bn[c] = sc;
    bn[nch + c] = b[c] - mean * sc;
}

// ---------------------------------------------------------------------------
// Layer2 (HMMA): per (b-tile, cb, j): 128 x 128, K=384 in 4 chunks of 96,
// 3 passes per chunk. A and B staging both pure uint4 copies.
// ---------------------------------------------------------------------------
__global__ void __launch_bounds__(256, 2) k_layer2() {
    extern __shared__ __align__(16) char dsm[];
    char* Ah = dsm;
    char* Al = dsm + 26624;
    char* Bh = dsm + 53248;
    char* Bl = dsm + 79872;
    const int t = threadIdx.x, lane = t & 31, w = t >> 5;
    const int b0 = blockIdx.x * 128;
    const int cb = blockIdx.y;
    const int j  = blockIdx.z;

    float d[2][8][4];
    #pragma unroll
    for (int mt = 0; mt < 2; mt++)
        #pragma unroll
        for (int nt = 0; nt < 8; nt++)
            #pragma unroll
            for (int e = 0; e < 4; e++) d[mt][nt][e] = 0.f;

    const int R0 = (w & 3) * 32, C0 = (w >> 2) * 64;
    const unsigned offA = (unsigned)((R0 + (lane & 7) + ((lane >> 3) & 1) * 8) * 208 + ((lane >> 4) & 1) * 16);
    const unsigned offB = (unsigned)((C0 + (lane & 7) + ((lane >> 4) & 1) * 8) * 208 + ((lane >> 3) & 1) * 16);
    const unsigned bAh = smem_u32(Ah), bAl = smem_u32(Al);
    const unsigned bBh = smem_u32(Bh), bBl = smem_u32(Bl);

    for (int kt = 0; kt < 4; kt++) {
        __syncthreads();
        // stage A chunk: [row][k 96] from g_t1h/g_t1l (16B copies)
        for (int i = t; i < 1536; i += 256) {
            int r = i & 127, m = i >> 7;        // m 0..11
            int cc = m / 3, rr = m - cc * 3;
            long src = (long)(b0 + r) * 1152 + (j + rr) * 128 + (kt * 4 + cc) * 8;
            int doff = r * 208 + (cc * 24 + rr * 8) * 2;
            *reinterpret_cast<uint4*>(Ah + doff) = *reinterpret_cast<const uint4*>(g_t1h + src);
            *reinterpret_cast<uint4*>(Al + doff) = *reinterpret_cast<const uint4*>(g_t1l + src);
        }
        // stage B chunk: uint4 copies from g_A2h/g_A2l [j][col][k]
        for (int i = t; i < 1536; i += 256) {
            int col = i / 12, q = i - col * 12;
            long src = (long)(j * 256 + cb * 128 + col) * 384 + kt * 96 + q * 8;
            int doff = col * 208 + q * 16;
            *reinterpret_cast<uint4*>(Bh + doff) = *reinterpret_cast<const uint4*>(g_A2h + src);
            *reinterpret_cast<uint4*>(Bl + doff) = *reinterpret_cast<const uint4*>(g_A2l + src);
        }
        __syncthreads();

        for (int pass = 0; pass < 3; pass++) {
            unsigned aB = (pass == 1 ? bAl : bAh) + offA;
            unsigned bB = (pass == 2 ? bBl : bBh) + offB;
            #pragma unroll
            for (int ks = 0; ks < 6; ks++) {
                unsigned A0[4], A1[4];
                ldsm4(A0, aB + ks * 32);
                ldsm4(A1, aB + 16 * 208 + ks * 32);
                #pragma unroll
                for (int ntp = 0; ntp < 4; ntp++) {
                    unsigned Bf[4];
                    ldsm4(Bf, bB + ntp * (16 * 208) + ks * 32);
                    mma16816(d[0][2 * ntp],     A0, Bf[0], Bf[1]);
                    mma16816(d[1][2 * ntp],     A1, Bf[0], Bf[1]);
                    mma16816(d[0][2 * ntp + 1], A0, Bf[2], Bf[3]);
                    mma16816(d[1][2 * ntp + 1], A1, Bf[2], Bf[3]);
                }
            }
        }
    }
    __syncthreads();

    // spill to pre[128][132] with bias2 added
    float* pre = reinterpret_cast<float*>(dsm);
    const int lr = lane >> 2, lc2 = (lane & 3) * 2;
    #pragma unroll
    for (int mt = 0; mt < 2; mt++)
        #pragma unroll
        for (int nt = 0; nt < 8; nt++) {
            int col = C0 + 8 * nt + lc2;
            float2 bv = *reinterpret_cast<const float2*>(g_bias2 + j * 256 + cb * 128 + col);
            int row = R0 + 16 * mt + lr;
            *reinterpret_cast<float2*>(pre + row * 132 + col) =
                make_float2(d[mt][nt][0] + bv.x, d[mt][nt][1] + bv.y);
            *reinterpret_cast<float2*>(pre + (row + 8) * 132 + col) =
                make_float2(d[mt][nt][2] + bv.x, d[mt][nt][3] + bv.y);
        }
    __syncthreads();

    // Pool(4,s2,p1)+relu+stats -> transposed g_t2[idx][b]
    const int row = t & 127, half = t >> 7;
    const float* pr = pre + row * 132;
    #pragma unroll
    for (int ol = 0; ol < 8; ol++) {
        int lc = half * 8 + ol;
        int o2g = cb * 16 + lc;
        float s = 0.f, ss = 0.f;
        #pragma unroll
        for (int k = 0; k < 4; k++) {
            int lo = (2 * k - 1 < 0) ? 0 : 2 * k - 1;
            int hi = (2 * k + 2 > 7) ? 7 : 2 * k + 2;
            float m = pr[lc * 8 + lo];
            for (int nn = lo + 1; nn <= hi; nn++) m = fmaxf(m, pr[lc * 8 + nn]);
            m = fmaxf(m, 0.f);
            g_t2[(long)(o2g * 28 + j * 4 + k) * 4096 + b0 + row] = m;
            s += m; ss += m * m;
        }
        float sA = warp_sum(s), ssA = warp_sum(ss);
        if ((t & 31) == 0) { atomicAdd(&g_red[32 + o2g], sA); atomicAdd(&g_red[64 + o2g], ssA); }
    }
}

// ---------------------------------------------------------------------------
// Layer3: f32x2 row-pair (unchanged). smem 96256 B, 2 blocks/SM.
// ---------------------------------------------------------------------------
__global__ void __launch_bounds__(256, 2) k_layer3() {
    extern __shared__ float sm[];
    float* actsT = sm;             // [896][20]
    float* ws    = sm + 17920;     // [96][64]
    __shared__ float st[128];
    const int t = threadIdx.x;
    const int b0 = blockIdx.x * 16;

    for (int i = t; i < 3584; i += 256) {
        int idx = i >> 2, r4 = (i & 3) * 4;
        float4 v = *reinterpret_cast<const float4*>(g_t2 + (long)idx * 4096 + b0 + r4);
        *reinterpret_cast<float4*>(actsT + idx * 20 + r4) = v;
    }
    for (int i = t; i < 6144; i += 256) ws[i] = g_w3f[i];
    if (t < 128) st[t] = 0.f;
    __syncthreads();

    const int o3 = t & 63, rpg = t >> 6;
    const ull* a64 = reinterpret_cast<const ull*>(actsT);
    const float invj[5] = {1.f, 0.5f, 0.25f, 0.125f, 0.0625f};
    const float bias = g_bias3[o3];
    float s = 0.f, ssq = 0.f;

    #pragma unroll
    for (int hf = 0; hf < 2; hf++) {
        const int rp = rpg + 4 * hf;
        ull accp[15];
        #pragma unroll
        for (int i = 0; i < 15; i++) accp[i] = 0ull;

        for (int c = 0; c < 32; c++) {
            ull av[21];
            #pragma unroll
            for (int m = 0; m < 7; m++)
                #pragma unroll
                for (int l = 0; l < 3; l++)
                    av[m * 3 + l] = a64[(c * 28 + m * 4 + l) * 10 + rp];
            ull w0 = dup2(ws[(c * 3 + 0) * 64 + o3]);
            ull w1 = dup2(ws[(c * 3 + 1) * 64 + o3]);
            ull w2 = dup2(ws[(c * 3 + 2) * 64 + o3]);
            #pragma unroll
            for (int jj = 0; jj < 5; jj++)
                #pragma unroll
                for (int l = 0; l < 3; l++) {
                    fma2(accp[jj * 3 + l], w0, av[(jj + 0) * 3 + l]);
                    fma2(accp[jj * 3 + l], w1, av[(jj + 1) * 3 + l]);
                    fma2(accp[jj * 3 + l], w2, av[(jj + 2) * 3 + l]);
                }
        }
        #pragma unroll
        for (int jj = 0; jj < 5; jj++) {
            float2 v0 = *reinterpret_cast<float2*>(&accp[jj * 3 + 0]);
            float2 v1 = *reinterpret_cast<float2*>(&accp[jj * 3 + 1]);
            float2 v2 = *reinterpret_cast<float2*>(&accp[jj * 3 + 2]);
            float mx = (fmaxf(fmaxf(v0.x, v1.x), v2.x) + bias) * invj[jj];
            float my = (fmaxf(fmaxf(v0.y, v1.y), v2.y) + bias) * invj[jj];
            mx = fmaxf(mx, 0.f); my = fmaxf(my, 0.f);
            *reinterpret_cast<float2*>(g_t3 + (long)(o3 * 5 + jj) * 4096 + b0 + 2 * rp) =
                make_float2(mx, my);
            s += mx + my; ssq += mx * mx + my * my;
        }
    }
    atomicAdd(&st[o3], s);
    atomicAdd(&st[64 + o3], ssq);
    __syncthreads();
    if (t < 64) { atomicAdd(&g_red[96 + t], st[t]); atomicAdd(&g_red[160 + t], st[64 + t]); }
}

// 3-layer MLP; BN3 prefolded. Unchanged.
__global__ void __launch_bounds__(128) k_fc(const float* __restrict__ fw2, const float* __restrict__ fb2,
                                            const float* __restrict__ fw3, const float* __restrict__ fb3,
                                            float* __restrict__ out) {
    __shared__ float w1s[5120];
    __shared__ float vtT[32 * 132];
    __shared__ float w2s[256];
    __shared__ float w3s[272];
    __shared__ float b1s[16], b2s[16], b3s[17];
    int t = threadIdx.x;
    int bbase = blockIdx.x * 128;
    for (int i = t; i < 5120; i += 128) w1s[i] = g_fw1f[i];
    for (int i = t; i < 256; i += 128) w2s[i] = fw2[i];
    for (int i = t; i < 272; i += 128) w3s[i] = fw3[i];
    if (t < 16) { b1s[t] = g_fb1f[t]; b2s[t] = fb2[t]; }
    if (t < 17) b3s[t] = fb3[t];
    __syncthreads();

    float h1[16];
    #pragma unroll
    for (int o = 0; o < 16; o++) h1[o] = b1s[o];

    for (int i0 = 0; i0 < 320; i0 += 32) {
        __syncthreads();
        for (int i = t; i < 1024; i += 128) {
            int c2 = i >> 5, r4 = (i & 31) * 4;
            float4 v = *reinterpret_cast<const float4*>(g_t3 + (long)(i0 + c2) * 4096 + bbase + r4);
            *reinterpret_cast<float4*>(vtT + c2 * 132 + r4) = v;
        }
        __syncthreads();
        #pragma unroll 4
        for (int c2 = 0; c2 < 32; c2++) {
            float v = vtT[c2 * 132 + t];
            const float* wr = &w1s[(i0 + c2) * 16];
            #pragma unroll
            for (int o = 0; o < 16; o++) h1[o] += v * wr[o];
        }
    }
    float h2[16];
    #pragma unroll
    for (int o = 0; o < 16; o++) {
        float a = b2s[o];
        #pragma unroll
        for (int k = 0; k < 16; k++) a += h1[k] * w2s[o * 16 + k];
        h2[o] = a;
    }
    int b = bbase + t;
    #pragma unroll
    for (int o = 0; o < 17; o++) {
        float a = b3s[o];
        #pragma unroll
        for (int k = 0; k < 16; k++) a += h2[k] * w3s[o * 16 + k];
        out[b * 17 + o] = a;
    }
}

extern "C" void kernel_launch(void* const* d_in, const int* in_sizes, int n_in,
                              void* d_out, int out_size) {
    const float* x   = (const float*)d_in[0];
    const float* w1  = (const float*)d_in[1];
    const float* w2  = (const float*)d_in[2];
    const float* w3  = (const float*)d_in[3];
    const float* g1  = (const float*)d_in[4];
    const float* b1  = (const float*)d_in[5];
    const float* g2  = (const float*)d_in[6];
    const float* b2  = (const float*)d_in[7];
    const float* g3  = (const float*)d_in[8];
    const float* b3  = (const float*)d_in[9];
    const float* fw1 = (const float*)d_in[10];
    const float* fb1 = (const float*)d_in[11];
    const float* fw2 = (const float*)d_in[12];
    const float* fb2 = (const float*)d_in[13];
    const float* fw3 = (const float*)d_in[14];
    const float* fb3 = (const float*)d_in[15];
    float* out = (float*)d_out;

    cudaFuncSetAttribute(k_layer1, cudaFuncAttributeMaxDynamicSharedMemorySize, 106496);
    cudaFuncSetAttribute(k_layer2, cudaFuncAttributeMaxDynamicSharedMemorySize, 106496);
    cudaFuncSetAttribute(k_layer3, cudaFuncAttributeMaxDynamicSharedMemorySize, 96256);

    k_zero<<<1, 256>>>();
    k_prep1<<<(221184 + 255) / 256, 256>>>(w1);
    k_prep2<<<(688128 + 255) / 256, 256>>>(w2);
    k_layer1<<<dim3(32, 18), 256, 106496>>>(x);
    k_bnparam<<<1, 64>>>(g1, b1, 1);
    k_bias2<<<7, 256>>>();
    k_conv2<<<2688, 256>>>();
    k_layer2<<<dim3(32, 2, 7), 256, 106496>>>();
    k_bnparam<<<1, 64>>>(g2, b2, 2);
    k_fold3<<<24, 256>>>(w3);
    k_layer3<<<256, 256, 96256>>>();
    k_bnparam<<<1, 64>>>(g3, b3, 3);
    k_foldfc<<<21, 256>>>(fw1, fb1);
    k_fc<<<32, 128>>>(fw2, fb2, fw3, fb3, out);
}